// round 1
// baseline (speedup 1.0000x reference)
#include <cuda_runtime.h>
#include <cstdint>

#define NN 50000
#define FF 602
#define HH 32
#define CC 41

// ---------------- scratch (device globals; no runtime allocation) ------------
__device__ float g_y[NN * HH];     // x @ W1a
__device__ float g_pre1[NN * HH];  // y + b1a  (+ scatter)
__device__ float g_t1[NN * HH];    // relu(pre1) @ W1b + b1b
__device__ float g_z2[NN * HH];    // h1 @ W2a
__device__ float g_pre2[NN * HH];  // z2 + b2a (+ scatter)
__device__ float g_t2[NN * HH];    // relu(pre2) @ W2b + b2b
__device__ float g_stats[4 * HH];  // [sum1, sq1, sum2, sq2]

__global__ void zero_stats_kernel() {
    if (threadIdx.x < 4 * HH) g_stats[threadIdx.x] = 0.f;
}

// ---------------- K1: y = x @ W1a ; pre1 = y + b1a ---------------------------
// 64 rows x 32 cols per block, 128 threads; packed f32x2 FMAs (2 rows/instr).
#define GBM 64
#define GBK 32

__global__ __launch_bounds__(128) void gemm_x_kernel(
    const float* __restrict__ x, const float* __restrict__ W,
    const float* __restrict__ bias, int nrows) {
    __shared__ __align__(16) float Xs[GBK][GBM + 2];          // transposed, pad=66
    __shared__ __align__(16) unsigned long long Wdup[GBK][HH]; // (w,w) packed
    int tid = threadIdx.x;
    int c2 = tid & 15;   // column pair 0..15 -> cols 2c2, 2c2+1
    int rg = tid >> 4;   // row group 0..7   -> rows rg*8 .. rg*8+7
    int row0 = blockIdx.x * GBM;

    unsigned long long acc[4][2];
#pragma unroll
    for (int i = 0; i < 4; i++) { acc[i][0] = 0ULL; acc[i][1] = 0ULL; }

    for (int k0 = 0; k0 < FF; k0 += GBK) {
        for (int i = tid; i < GBM * GBK; i += 128) {
            int r = i >> 5, k = i & 31;
            int gr = row0 + r, gk = k0 + k;
            Xs[k][r] = (gr < nrows && gk < FF) ? x[(size_t)gr * FF + gk] : 0.f;
        }
        for (int i = tid; i < GBK * HH; i += 128) {
            int k = i >> 5, c = i & 31;
            int gk = k0 + k;
            float w = (gk < FF) ? W[gk * HH + c] : 0.f;
            unsigned int wu = __float_as_uint(w);
            unsigned long long wp;
            asm("mov.b64 %0, {%1, %1};" : "=l"(wp) : "r"(wu));
            Wdup[k][c] = wp;
        }
        __syncthreads();
#pragma unroll 4
        for (int k = 0; k < GBK; k++) {
            unsigned long long w0 = Wdup[k][2 * c2];
            unsigned long long w1 = Wdup[k][2 * c2 + 1];
            const unsigned long long* xr =
                (const unsigned long long*)&Xs[k][rg * 8];
#pragma unroll
            for (int i = 0; i < 4; i++) {
                unsigned long long a = xr[i];
                asm("fma.rn.f32x2 %0, %1, %2, %0;" : "+l"(acc[i][0]) : "l"(a), "l"(w0));
                asm("fma.rn.f32x2 %0, %1, %2, %0;" : "+l"(acc[i][1]) : "l"(a), "l"(w1));
            }
        }
        __syncthreads();
    }

    float b0 = bias[2 * c2], b1 = bias[2 * c2 + 1];
#pragma unroll
    for (int i = 0; i < 4; i++) {
        unsigned int l0, h0, l1, h1;
        asm("mov.b64 {%0, %1}, %2;" : "=r"(l0), "=r"(h0) : "l"(acc[i][0]));
        asm("mov.b64 {%0, %1}, %2;" : "=r"(l1), "=r"(h1) : "l"(acc[i][1]));
        int r0 = row0 + rg * 8 + 2 * i;
        if (r0 < nrows) {
            float f0 = __uint_as_float(l0), f1 = __uint_as_float(l1);
            *(float2*)&g_y[(size_t)r0 * HH + 2 * c2] = make_float2(f0, f1);
            *(float2*)&g_pre1[(size_t)r0 * HH + 2 * c2] = make_float2(f0 + b0, f1 + b1);
        }
        int r1 = r0 + 1;
        if (r1 < nrows) {
            float f0 = __uint_as_float(h0), f1 = __uint_as_float(h1);
            *(float2*)&g_y[(size_t)r1 * HH + 2 * c2] = make_float2(f0, f1);
            *(float2*)&g_pre1[(size_t)r1 * HH + 2 * c2] = make_float2(f0 + b0, f1 + b1);
        }
    }
}

// ---------------- K2/K5: scatter  dst[row] += src[col]  (32 floats/edge) -----
// 8 threads per edge, each does one float4 gather + one red.global.add.v4.f32.
__global__ __launch_bounds__(256) void scatter_kernel(
    const int* __restrict__ rowi, const int* __restrict__ coli, int phase, int E) {
    const float* src = phase ? g_z2 : g_y;
    float* dst = phase ? g_pre2 : g_pre1;
    int t = blockIdx.x * blockDim.x + threadIdx.x;
    int e = t >> 3, q = t & 7;
    if (e >= E) return;
    int r = __ldg(rowi + e);
    int c = __ldg(coli + e);
    float4 v = __ldg((const float4*)(src + (size_t)c * HH) + q);
    float* p = dst + (size_t)r * HH + q * 4;
    asm volatile("red.global.add.v4.f32 [%0], {%1,%2,%3,%4};"
                 :: "l"(p), "f"(v.x), "f"(v.y), "f"(v.z), "f"(v.w) : "memory");
}

// ---------------- K3/K6: t = relu(pre) @ W + b ; accumulate BN stats ---------
__global__ __launch_bounds__(256) void mlp_kernel(
    const float* __restrict__ W, const float* __restrict__ b, int phase, int nrows) {
    const float* in = phase ? g_pre2 : g_pre1;
    float* out = phase ? g_t2 : g_t1;
    int soff = phase ? 2 * HH : 0;
    __shared__ float Ws[HH][HH];
    __shared__ float ssum[8][HH], ssq[8][HH];
    int tid = threadIdx.x, lane = tid & 31, w = tid >> 5;
    for (int i = tid; i < HH * HH; i += 256) Ws[i >> 5][i & 31] = W[i];
    __syncthreads();
    float bl = b[lane];
    float lsum = 0.f, lsq = 0.f;
    int warp = (blockIdx.x * 256 + tid) >> 5;
    int nw = (gridDim.x * 256) >> 5;
    for (int r = warp; r < nrows; r += nw) {
        float v = fmaxf(in[(size_t)r * HH + lane], 0.f);
        float acc = bl;
#pragma unroll
        for (int k = 0; k < HH; k++)
            acc += __shfl_sync(0xffffffffu, v, k) * Ws[k][lane];
        out[(size_t)r * HH + lane] = acc;
        lsum += acc; lsq += acc * acc;
    }
    ssum[w][lane] = lsum; ssq[w][lane] = lsq;
    __syncthreads();
    if (w == 0) {
        float s = 0.f, q = 0.f;
#pragma unroll
        for (int i = 0; i < 8; i++) { s += ssum[i][lane]; q += ssq[i][lane]; }
        atomicAdd(&g_stats[soff + lane], s);
        atomicAdd(&g_stats[soff + HH + lane], q);
    }
}

// ---------------- K4: h1 = BN(t1) ; z2 = h1 @ W2a ; pre2 = z2 + b2a ----------
__global__ __launch_bounds__(256) void bn1_gemm_kernel(
    const float* __restrict__ g1, const float* __restrict__ be1,
    const float* __restrict__ W2a, const float* __restrict__ b2a, int nrows) {
    __shared__ float Ws[HH][HH];
    int tid = threadIdx.x, lane = tid & 31;
    for (int i = tid; i < HH * HH; i += 256) Ws[i >> 5][i & 31] = W2a[i];
    __syncthreads();
    float nf = (float)nrows;
    float m = g_stats[lane] / nf;
    float var = g_stats[HH + lane] / nf - m * m;
    float sc = rsqrtf(var + 1e-5f) * g1[lane];
    float sh = be1[lane] - m * sc;
    float bl = b2a[lane];
    int warp = (blockIdx.x * 256 + tid) >> 5;
    int nw = (gridDim.x * 256) >> 5;
    for (int r = warp; r < nrows; r += nw) {
        float h = g_t1[(size_t)r * HH + lane] * sc + sh;
        float acc = 0.f;
#pragma unroll
        for (int k = 0; k < HH; k++)
            acc += __shfl_sync(0xffffffffu, h, k) * Ws[k][lane];
        g_z2[(size_t)r * HH + lane] = acc;
        g_pre2[(size_t)r * HH + lane] = acc + bl;
    }
}

// ---------------- K7: h2 = BN(t2); f = relu(h2@Wf1+bf1); out = f@Wf2+bf2 -----
__global__ __launch_bounds__(256) void final_kernel(
    const float* __restrict__ g2, const float* __restrict__ be2,
    const float* __restrict__ Wf1, const float* __restrict__ bf1,
    const float* __restrict__ Wf2, const float* __restrict__ bf2,
    float* __restrict__ out, int nrows) {
    __shared__ float W1s[HH][HH];
    __shared__ float W2s[HH][48];
    int tid = threadIdx.x, lane = tid & 31;
    for (int i = tid; i < HH * HH; i += 256) W1s[i >> 5][i & 31] = Wf1[i];
    for (int i = tid; i < HH * CC; i += 256) W2s[i / CC][i % CC] = Wf2[i];
    __syncthreads();
    float nf = (float)nrows;
    float m = g_stats[2 * HH + lane] / nf;
    float var = g_stats[3 * HH + lane] / nf - m * m;
    float sc = rsqrtf(var + 1e-5f) * g2[lane];
    float sh = be2[lane] - m * sc;
    float b1 = bf1[lane];
    float bo0 = bf2[lane];
    int has2 = (lane < CC - HH);
    float bo1 = has2 ? bf2[HH + lane] : 0.f;
    int c1 = has2 ? (HH + lane) : HH;  // safe index for inactive lanes
    int warp = (blockIdx.x * 256 + tid) >> 5;
    int nw = (gridDim.x * 256) >> 5;
    for (int r = warp; r < nrows; r += nw) {
        float h = g_t2[(size_t)r * HH + lane] * sc + sh;
        float f = b1;
#pragma unroll
        for (int k = 0; k < HH; k++)
            f += __shfl_sync(0xffffffffu, h, k) * W1s[k][lane];
        f = fmaxf(f, 0.f);
        float o0 = bo0, o1 = bo1;
#pragma unroll
        for (int k = 0; k < HH; k++) {
            float a = __shfl_sync(0xffffffffu, f, k);
            o0 += a * W2s[k][lane];
            o1 += a * W2s[k][c1];
        }
        out[(size_t)r * CC + lane] = o0;
        if (has2) out[(size_t)r * CC + HH + lane] = o1;
    }
}

// ---------------- launch -----------------------------------------------------
extern "C" void kernel_launch(void* const* d_in, const int* in_sizes, int n_in,
                              void* d_out, int out_size) {
    const float* x   = (const float*)d_in[0];
    const int*   row = (const int*)d_in[1];
    const int*   col = (const int*)d_in[2];
    const float* W1a = (const float*)d_in[3];
    const float* b1a = (const float*)d_in[4];
    const float* W1b = (const float*)d_in[5];
    const float* b1b = (const float*)d_in[6];
    const float* g1  = (const float*)d_in[7];
    const float* be1 = (const float*)d_in[8];
    const float* W2a = (const float*)d_in[9];
    const float* b2a = (const float*)d_in[10];
    const float* W2b = (const float*)d_in[11];
    const float* b2b = (const float*)d_in[12];
    const float* g2  = (const float*)d_in[13];
    const float* be2 = (const float*)d_in[14];
    const float* Wf1 = (const float*)d_in[15];
    const float* bf1 = (const float*)d_in[16];
    const float* Wf2 = (const float*)d_in[17];
    const float* bf2 = (const float*)d_in[18];
    float* out = (float*)d_out;

    int nrows = in_sizes[0] / FF;
    int E = in_sizes[1];
    long long st = (long long)E * 8;
    int sgrid = (int)((st + 255) / 256);

    zero_stats_kernel<<<1, 128>>>();
    gemm_x_kernel<<<(nrows + GBM - 1) / GBM, 128>>>(x, W1a, b1a, nrows);
    scatter_kernel<<<sgrid, 256>>>(row, col, 0, E);
    mlp_kernel<<<416, 256>>>(W1b, b1b, 0, nrows);
    bn1_gemm_kernel<<<416, 256>>>(g1, be1, W2a, b2a, nrows);
    scatter_kernel<<<sgrid, 256>>>(row, col, 1, E);
    mlp_kernel<<<416, 256>>>(W2b, b2b, 1, nrows);
    final_kernel<<<416, 256>>>(g2, be2, Wf1, bf1, Wf2, bf2, out, nrows);
}

// round 3
// speedup vs baseline: 1.0519x; 1.0519x over previous
#include <cuda_runtime.h>
#include <cstdint>

#define NN 50000
#define FF 602
#define HH 32
#define CC 41
typedef unsigned long long u64;

// ---------------- scratch (device globals) -----------------------------------
__device__ float g_y[NN * HH];     // x @ W1a                (scatter src 1)
__device__ float g_pre1[NN * HH];  // y + b1a + agg
__device__ float g_t1[NN * HH];    // relu(pre1) @ W1b + b1b
__device__ float g_z2[NN * HH];    // h1 @ W2a               (scatter src 2)
__device__ float g_pre2[NN * HH];  // z2 + b2a + agg
__device__ float g_t2[NN * HH];    // relu(pre2) @ W2b + b2b
__device__ float g_stats[4 * HH];  // [sum1, sq1, sum2, sq2]
__device__ float g_WfA[HH * HH];   // diag(sc1) @ W2a
__device__ float g_WfF[HH * HH];   // diag(sc2) @ Wf1
__device__ float g_cA[HH];         // sh1 @ W2a            (z2 const)
__device__ float g_cB[HH];         // g_cA + b2a           (pre2 const)
__device__ float g_cF[HH];         // sh2 @ Wf1 + bf1

__device__ __forceinline__ u64 fdup(float v) {
    u64 d; unsigned u = __float_as_uint(v);
    asm("mov.b64 %0, {%1,%1};" : "=l"(d) : "r"(u));
    return d;
}
__device__ __forceinline__ float2 u2f(u64 v) {
    unsigned lo, hi;
    asm("mov.b64 {%0,%1}, %2;" : "=r"(lo), "=r"(hi) : "l"(v));
    return make_float2(__uint_as_float(lo), __uint_as_float(hi));
}
__device__ __forceinline__ void ffma2(u64& a, u64 x, u64 w) {
    asm("fma.rn.f32x2 %0, %1, %2, %0;" : "+l"(a) : "l"(x), "l"(w));
}

__global__ void zero_stats_kernel() {
    if (threadIdx.x < 4 * HH) g_stats[threadIdx.x] = 0.f;
}

// ---------------- K1: y = x @ W1a ; pre1 = y + b1a ---------------------------
// 128 rows x 32 cols per block, 128 threads. Thread = 8 rows x 4 cols.
// Cols packed in f32x2 (W pairs are contiguous in row-major W), rows duplicated
// into (x,x) u64s in smem. Per k: 4 LDS.128 (x) + 1 LDS.128 (w) + 16 FFMA2.
__global__ __launch_bounds__(128) void gemm_x_kernel(
    const float* __restrict__ x, const float* __restrict__ W,
    const float* __restrict__ bias, int nrows) {
    __shared__ __align__(16) u64 Xd[32][130];
    __shared__ __align__(16) u64 Ws[32][16];
    int tid = threadIdx.x;
    int cg = tid & 7, rg = tid >> 3;
    int row0 = blockIdx.x * 128;

    u64 acc[8][2];
#pragma unroll
    for (int i = 0; i < 8; i++) { acc[i][0] = 0; acc[i][1] = 0; }

    for (int k0 = 0; k0 < FF; k0 += 32) {
        // stage W tile (32x32 floats, raw pairs)
        const float4* Wv = (const float4*)W;
        for (int i = tid; i < 256; i += 128) {
            int k = i >> 3, c4 = i & 7;
            int gk = k0 + k;
            float4 v = make_float4(0.f, 0.f, 0.f, 0.f);
            if (gk < FF) v = Wv[gk * 8 + c4];
            ((float4*)&Ws[k][0])[c4] = v;
        }
        // stage X tile transposed + duplicated
        for (int i = tid; i < 32 * 128; i += 128) {
            int k = i & 31, r = i >> 5;
            int gr = row0 + r, gk = k0 + k;
            float v = (gr < nrows && gk < FF) ? x[(size_t)gr * FF + gk] : 0.f;
            Xd[k][r] = fdup(v);
        }
        __syncthreads();
#pragma unroll
        for (int k = 0; k < 32; k++) {
            u64 xv[8];
#pragma unroll
            for (int h = 0; h < 4; h++)
                *(ulonglong2*)&xv[2 * h] = *(const ulonglong2*)&Xd[k][rg * 8 + 2 * h];
            ulonglong2 wv = *(const ulonglong2*)&Ws[k][cg * 2];
#pragma unroll
            for (int i = 0; i < 8; i++) {
                ffma2(acc[i][0], xv[i], wv.x);
                ffma2(acc[i][1], xv[i], wv.y);
            }
        }
        __syncthreads();
    }

    float2 b0 = *(const float2*)&bias[4 * cg];
    float2 b1 = *(const float2*)&bias[4 * cg + 2];
#pragma unroll
    for (int i = 0; i < 8; i++) {
        int r = row0 + rg * 8 + i;
        if (r < nrows) {
            float2 v0 = u2f(acc[i][0]);
            float2 v1 = u2f(acc[i][1]);
            *(float2*)&g_y[(size_t)r * HH + 4 * cg] = v0;
            *(float2*)&g_y[(size_t)r * HH + 4 * cg + 2] = v1;
            *(float2*)&g_pre1[(size_t)r * HH + 4 * cg] = make_float2(v0.x + b0.x, v0.y + b0.y);
            *(float2*)&g_pre1[(size_t)r * HH + 4 * cg + 2] = make_float2(v1.x + b1.x, v1.y + b1.y);
        }
    }
}

// ---------------- shared K=32 GEMM core --------------------------------------
__device__ __forceinline__ void stage_and_mm32(
    const float* __restrict__ in, const float* __restrict__ Wsrc, int relu_in,
    int nrows, int row0, int tid, int cg, int rg,
    u64 (*Xd)[130], u64 (*Ws)[16], u64 acc[8][2]) {
    const float4* Wv = (const float4*)Wsrc;
    for (int i = tid; i < 256; i += 128)
        ((float4*)&Ws[i >> 3][0])[i & 7] = Wv[i];
    for (int i = tid; i < 32 * 128; i += 128) {
        int k = i & 31, r = i >> 5;
        int gr = row0 + r;
        float v = (gr < nrows) ? in[(size_t)gr * HH + k] : 0.f;
        if (relu_in) v = fmaxf(v, 0.f);
        Xd[k][r] = fdup(v);
    }
    __syncthreads();
#pragma unroll
    for (int k = 0; k < 32; k++) {
        u64 xv[8];
#pragma unroll
        for (int h = 0; h < 4; h++)
            *(ulonglong2*)&xv[2 * h] = *(const ulonglong2*)&Xd[k][rg * 8 + 2 * h];
        ulonglong2 wv = *(const ulonglong2*)&Ws[k][cg * 2];
#pragma unroll
        for (int i = 0; i < 8; i++) {
            ffma2(acc[i][0], xv[i], wv.x);
            ffma2(acc[i][1], xv[i], wv.y);
        }
    }
}

// ---------------- K2/K5: scatter  dst[row] += src[col] -----------------------
__global__ __launch_bounds__(256) void scatter_kernel(
    const int* __restrict__ rowi, const int* __restrict__ coli, int phase, int E) {
    const float* src = phase ? g_z2 : g_y;
    float* dst = phase ? g_pre2 : g_pre1;
    int t = blockIdx.x * blockDim.x + threadIdx.x;
    int e = t >> 3, q = t & 7;
    if (e >= E) return;
    int r = __ldg(rowi + e);
    int c = __ldg(coli + e);
    float4 v = __ldg((const float4*)(src + (size_t)c * HH) + q);
    float* p = dst + (size_t)r * HH + q * 4;
    asm volatile("red.global.add.v4.f32 [%0], {%1,%2,%3,%4};"
                 :: "l"(p), "f"(v.x), "f"(v.y), "f"(v.z), "f"(v.w) : "memory");
}

// ---------------- K3/K6: t = relu(pre) @ W + b ; BN stats --------------------
__global__ __launch_bounds__(128) void mlp_kernel(
    const float* __restrict__ W, const float* __restrict__ b, int phase, int nrows) {
    __shared__ __align__(16) u64 Xd[32][130];
    __shared__ __align__(16) u64 Ws[32][16];
    const float* in = phase ? g_pre2 : g_pre1;
    float* out = phase ? g_t2 : g_t1;
    int soff = phase ? 2 * HH : 0;
    int tid = threadIdx.x, cg = tid & 7, rg = tid >> 3;
    int row0 = blockIdx.x * 128;
    u64 acc[8][2];
#pragma unroll
    for (int i = 0; i < 8; i++) { acc[i][0] = 0; acc[i][1] = 0; }
    stage_and_mm32(in, W, 1, nrows, row0, tid, cg, rg, Xd, Ws, acc);

    float2 b0 = *(const float2*)&b[4 * cg];
    float2 b1 = *(const float2*)&b[4 * cg + 2];
    float s0 = 0, s1 = 0, s2 = 0, s3 = 0, q0 = 0, q1 = 0, q2 = 0, q3 = 0;
#pragma unroll
    for (int i = 0; i < 8; i++) {
        int r = row0 + rg * 8 + i;
        if (r < nrows) {
            float2 v0 = u2f(acc[i][0]); v0.x += b0.x; v0.y += b0.y;
            float2 v1 = u2f(acc[i][1]); v1.x += b1.x; v1.y += b1.y;
            *(float2*)&out[(size_t)r * HH + 4 * cg] = v0;
            *(float2*)&out[(size_t)r * HH + 4 * cg + 2] = v1;
            s0 += v0.x; q0 += v0.x * v0.x; s1 += v0.y; q1 += v0.y * v0.y;
            s2 += v1.x; q2 += v1.x * v1.x; s3 += v1.y; q3 += v1.y * v1.y;
        }
    }
    __syncthreads();
    float* sb = (float*)Xd;
    int c0 = 4 * cg;
    sb[rg * 32 + c0] = s0;       sb[rg * 32 + c0 + 1] = s1;
    sb[rg * 32 + c0 + 2] = s2;   sb[rg * 32 + c0 + 3] = s3;
    sb[512 + rg * 32 + c0] = q0;     sb[512 + rg * 32 + c0 + 1] = q1;
    sb[512 + rg * 32 + c0 + 2] = q2; sb[512 + rg * 32 + c0 + 3] = q3;
    __syncthreads();
    if (tid < 64) {
        int c = tid & 31, which = tid >> 5;
        float t = 0.f;
#pragma unroll
        for (int g2 = 0; g2 < 16; g2++) t += sb[which * 512 + g2 * 32 + c];
        atomicAdd(&g_stats[soff + which * HH + c], t);
    }
}

// ---------------- fold: BN into next weight matrix ---------------------------
__global__ void fold_kernel(const float* __restrict__ W, const float* __restrict__ g,
                            const float* __restrict__ be, const float* __restrict__ badd,
                            float* __restrict__ Wout, float* __restrict__ c0,
                            float* __restrict__ c1, int soff, float invn) {
    __shared__ float sc[HH], sh[HH], prod[HH][HH + 1];
    int tid = threadIdx.x;  // 1024
    int k = tid >> 5, c = tid & 31;
    if (tid < HH) {
        float m = g_stats[soff + tid] * invn;
        float v = g_stats[soff + HH + tid] * invn - m * m;
        float s = rsqrtf(v + 1e-5f) * g[tid];
        sc[tid] = s;
        sh[tid] = be[tid] - m * s;
    }
    __syncthreads();
    float w = W[k * HH + c];
    Wout[k * HH + c] = sc[k] * w;
    prod[k][c] = sh[k] * w;
    __syncthreads();
    if (tid < HH) {
        float s = 0.f;
#pragma unroll
        for (int kk = 0; kk < HH; kk++) s += prod[kk][tid];
        if (c0) c0[tid] = s;
        c1[tid] = s + badd[tid];
    }
}

// ---------------- K4: z2 = t1 @ WfA + cA ; pre2 = z2 + b2a -------------------
__global__ __launch_bounds__(128) void gemmb_kernel(int nrows) {
    __shared__ __align__(16) u64 Xd[32][130];
    __shared__ __align__(16) u64 Ws[32][16];
    int tid = threadIdx.x, cg = tid & 7, rg = tid >> 3;
    int row0 = blockIdx.x * 128;
    u64 acc[8][2];
#pragma unroll
    for (int i = 0; i < 8; i++) { acc[i][0] = 0; acc[i][1] = 0; }
    stage_and_mm32(g_t1, g_WfA, 0, nrows, row0, tid, cg, rg, Xd, Ws, acc);
    float2 a0 = *(const float2*)&g_cA[4 * cg];
    float2 a1 = *(const float2*)&g_cA[4 * cg + 2];
    float2 p0 = *(const float2*)&g_cB[4 * cg];
    float2 p1 = *(const float2*)&g_cB[4 * cg + 2];
#pragma unroll
    for (int i = 0; i < 8; i++) {
        int r = row0 + rg * 8 + i;
        if (r < nrows) {
            float2 v0 = u2f(acc[i][0]);
            float2 v1 = u2f(acc[i][1]);
            *(float2*)&g_z2[(size_t)r * HH + 4 * cg] = make_float2(v0.x + a0.x, v0.y + a0.y);
            *(float2*)&g_z2[(size_t)r * HH + 4 * cg + 2] = make_float2(v1.x + a1.x, v1.y + a1.y);
            *(float2*)&g_pre2[(size_t)r * HH + 4 * cg] = make_float2(v0.x + p0.x, v0.y + p0.y);
            *(float2*)&g_pre2[(size_t)r * HH + 4 * cg + 2] = make_float2(v1.x + p1.x, v1.y + p1.y);
        }
    }
}

// ---------------- K7: f = relu(t2 @ WfF + cF) ; out = f @ Wf2 + bf2 ----------
__global__ __launch_bounds__(128) void final_kernel(
    const float* __restrict__ Wf2, const float* __restrict__ bf2,
    float* __restrict__ out, int nrows) {
    __shared__ __align__(16) u64 Xd[32][130];
    __shared__ __align__(16) u64 Ws[32][16];
    __shared__ __align__(16) u64 W2[32][24];
    int tid = threadIdx.x, cg = tid & 7, rg = tid >> 3;
    int row0 = blockIdx.x * 128;

    // stage Wf2 padded to 48 cols
    float* W2f = (float*)W2;
    for (int i = tid; i < 32 * 48; i += 128) {
        int k = i / 48, c = i - k * 48;
        W2f[k * 48 + c] = (c < CC) ? Wf2[k * CC + c] : 0.f;
    }

    u64 acc[8][2];
#pragma unroll
    for (int i = 0; i < 8; i++) { acc[i][0] = 0; acc[i][1] = 0; }
    stage_and_mm32(g_t2, g_WfF, 0, nrows, row0, tid, cg, rg, Xd, Ws, acc);

    float2 cf0 = *(const float2*)&g_cF[4 * cg];
    float2 cf1 = *(const float2*)&g_cF[4 * cg + 2];
    __syncthreads();  // done reading Xd from first gemm
#pragma unroll
    for (int i = 0; i < 8; i++) {
        int r = rg * 8 + i;
        float2 v0 = u2f(acc[i][0]);
        float2 v1 = u2f(acc[i][1]);
        Xd[4 * cg][r]     = fdup(fmaxf(v0.x + cf0.x, 0.f));
        Xd[4 * cg + 1][r] = fdup(fmaxf(v0.y + cf0.y, 0.f));
        Xd[4 * cg + 2][r] = fdup(fmaxf(v1.x + cf1.x, 0.f));
        Xd[4 * cg + 3][r] = fdup(fmaxf(v1.y + cf1.y, 0.f));
    }
    __syncthreads();

    u64 acc2[8][3];
#pragma unroll
    for (int i = 0; i < 8; i++) { acc2[i][0] = 0; acc2[i][1] = 0; acc2[i][2] = 0; }
#pragma unroll
    for (int k = 0; k < 32; k++) {
        u64 xv[8];
#pragma unroll
        for (int h = 0; h < 4; h++)
            *(ulonglong2*)&xv[2 * h] = *(const ulonglong2*)&Xd[k][rg * 8 + 2 * h];
        u64 w0 = W2[k][cg * 3], w1 = W2[k][cg * 3 + 1], w2 = W2[k][cg * 3 + 2];
#pragma unroll
        for (int i = 0; i < 8; i++) {
            ffma2(acc2[i][0], xv[i], w0);
            ffma2(acc2[i][1], xv[i], w1);
            ffma2(acc2[i][2], xv[i], w2);
        }
    }

    float bb[6];
#pragma unroll
    for (int j = 0; j < 3; j++) {
        int c = 2 * (cg * 3 + j);
        bb[2 * j]     = (c < CC)     ? bf2[c]     : 0.f;
        bb[2 * j + 1] = (c + 1 < CC) ? bf2[c + 1] : 0.f;
    }
#pragma unroll
    for (int i = 0; i < 8; i++) {
        int r = row0 + rg * 8 + i;
        if (r < nrows) {
#pragma unroll
            for (int j = 0; j < 3; j++) {
                int c = 2 * (cg * 3 + j);
                float2 v = u2f(acc2[i][j]);
                if (c < CC)     out[(size_t)r * CC + c]     = v.x + bb[2 * j];
                if (c + 1 < CC) out[(size_t)r * CC + c + 1] = v.y + bb[2 * j + 1];
            }
        }
    }
}

// ---------------- launch -----------------------------------------------------
extern "C" void kernel_launch(void* const* d_in, const int* in_sizes, int n_in,
                              void* d_out, int out_size) {
    const float* x   = (const float*)d_in[0];
    const int*   row = (const int*)d_in[1];
    const int*   col = (const int*)d_in[2];
    const float* W1a = (const float*)d_in[3];
    const float* b1a = (const float*)d_in[4];
    const float* W1b = (const float*)d_in[5];
    const float* b1b = (const float*)d_in[6];
    const float* g1  = (const float*)d_in[7];
    const float* be1 = (const float*)d_in[8];
    const float* W2a = (const float*)d_in[9];
    const float* b2a = (const float*)d_in[10];
    const float* W2b = (const float*)d_in[11];
    const float* b2b = (const float*)d_in[12];
    const float* g2  = (const float*)d_in[13];
    const float* be2 = (const float*)d_in[14];
    const float* Wf1 = (const float*)d_in[15];
    const float* bf1 = (const float*)d_in[16];
    const float* Wf2 = (const float*)d_in[17];
    const float* bf2 = (const float*)d_in[18];
    float* out = (float*)d_out;

    int nrows = in_sizes[0] / FF;
    int E = in_sizes[1];
    float invn = 1.f / (float)nrows;
    int g128 = (nrows + 127) / 128;
    long long st = (long long)E * 8;
    int sgrid = (int)((st + 255) / 256);

    float *d_WfA, *d_WfF, *d_cA, *d_cB, *d_cF;
    cudaGetSymbolAddress((void**)&d_WfA, g_WfA);
    cudaGetSymbolAddress((void**)&d_WfF, g_WfF);
    cudaGetSymbolAddress((void**)&d_cA, g_cA);
    cudaGetSymbolAddress((void**)&d_cB, g_cB);
    cudaGetSymbolAddress((void**)&d_cF, g_cF);

    zero_stats_kernel<<<1, 128>>>();
    gemm_x_kernel<<<g128, 128>>>(x, W1a, b1a, nrows);
    scatter_kernel<<<sgrid, 256>>>(row, col, 0, E);
    mlp_kernel<<<g128, 128>>>(W1b, b1b, 0, nrows);
    fold_kernel<<<1, 1024>>>(W2a, g1, be1, b2a, d_WfA, d_cA, d_cB, 0, invn);
    gemmb_kernel<<<g128, 128>>>(nrows);
    scatter_kernel<<<sgrid, 256>>>(row, col, 1, E);
    mlp_kernel<<<g128, 128>>>(W2b, b2b, 1, nrows);
    fold_kernel<<<1, 1024>>>(Wf1, g2, be2, bf1, d_WfF, (float*)0, d_cF, 2 * HH, invn);
    final_kernel<<<g128, 128>>>(Wf2, bf2, out, nrows);
}